// round 6
// baseline (speedup 1.0000x reference)
#include <cuda_runtime.h>
#include <cstdint>

#define BATCH   2
#define SEQ     2048
#define DMODEL  1024
#define NHEADS  16
#define HDIM    64
#define MROWS   (BATCH*SEQ)   // 4096

// -------- scratch (device globals; no allocation allowed) --------
__device__ float g_q[BATCH*NHEADS*SEQ*HDIM];   // [b][h][s][d]  (tf32-rounded)
__device__ float g_k[BATCH*NHEADS*SEQ*HDIM];
__device__ float g_v[BATCH*NHEADS*SEQ*HDIM];
__device__ float g_att[MROWS*DMODEL];          // merged [b][s][h*64+d] (tf32-rounded)
__device__ float g_x [MROWS*DMODEL];           // tf32-rounded X
__device__ float g_wq[DMODEL*DMODEL];          // tf32-rounded weights
__device__ float g_wk[DMODEL*DMODEL];
__device__ float g_wv[DMODEL*DMODEL];
__device__ float g_wo[DMODEL*DMODEL];

// ---------------- PTX helpers ----------------
__device__ __forceinline__ uint32_t s2u(const void* p) {
    return (uint32_t)__cvta_generic_to_shared(p);
}
__device__ __forceinline__ void cp16(uint32_t dst, const void* src) {
    asm volatile("cp.async.cg.shared.global [%0], [%1], 16;" :: "r"(dst), "l"(src));
}
__device__ __forceinline__ void cp_commit() {
    asm volatile("cp.async.commit_group;");
}
template<int N> __device__ __forceinline__ void cp_wait() {
    asm volatile("cp.async.wait_group %0;" :: "n"(N));
}
__device__ __forceinline__ void ldsm4(uint32_t* r, uint32_t addr) {
    asm volatile("ldmatrix.sync.aligned.m8n8.x4.shared.b16 {%0,%1,%2,%3}, [%4];"
                 : "=r"(r[0]), "=r"(r[1]), "=r"(r[2]), "=r"(r[3]) : "r"(addr));
}
// round-to-nearest tf32 (result is an fp32 bit pattern with rounded mantissa)
__device__ __forceinline__ float f2tf(float x) {
    uint32_t r;
    asm("cvt.rna.tf32.f32 %0, %1;" : "=r"(r) : "f"(x));
    return __uint_as_float(r);
}

// D += A * B  (m16n8k8, A row-major, B col-major, fp32 accum)
__device__ __forceinline__ void mma_tf32(float* d, const uint32_t* a, const uint32_t* b) {
    asm volatile(
        "mma.sync.aligned.m16n8k8.row.col.f32.tf32.tf32.f32 "
        "{%0,%1,%2,%3}, {%4,%5,%6,%7}, {%8,%9}, {%0,%1,%2,%3};\n"
        : "+f"(d[0]), "+f"(d[1]), "+f"(d[2]), "+f"(d[3])
        : "r"(a[0]), "r"(a[1]), "r"(a[2]), "r"(a[3]),
          "r"(b[0]), "r"(b[1]));
}

// ================= pre-pass: tf32-round inputs ==================
// z=0: X (4M floats), z=1..4: Wq/Wk/Wv/Wo (1M floats each)
__global__ __launch_bounds__(256)
void round_inputs(const float* __restrict__ X,
                  const float* __restrict__ Wq, const float* __restrict__ Wk,
                  const float* __restrict__ Wv, const float* __restrict__ Wo,
                  float* __restrict__ ox,
                  float* __restrict__ oq, float* __restrict__ ok,
                  float* __restrict__ ov, float* __restrict__ oo)
{
    const int z = blockIdx.z;
    const float* src = (z == 0) ? X : (z == 1) ? Wq : (z == 2) ? Wk : (z == 3) ? Wv : Wo;
    float* dst       = (z == 0) ? ox : (z == 1) ? oq : (z == 2) ? ok : (z == 3) ? ov : oo;
    const int n4 = (z == 0) ? (MROWS * DMODEL / 4) : (DMODEL * DMODEL / 4);
    const int idx = blockIdx.x * 256 + threadIdx.x;
    if (idx < n4) {
        float4 v = ((const float4*)src)[idx];
        v.x = f2tf(v.x); v.y = f2tf(v.y); v.z = f2tf(v.z); v.w = f2tf(v.w);
        ((float4*)dst)[idx] = v;
    }
}

// ================= GEMM (tf32 tensor core) core ==========
// M=4096, N=K=1024. Block 128x128, BK=16, 2-stage cp.async pipeline.
// 256 threads = 8 warps (2x4), warp tile 64x32. Inputs pre-rounded.
#define ASTR 20     // As[m][k] row stride (words)
#define BSTR 136    // Bs[k][n] row stride (words)

template<bool HEADOUT>
__device__ __forceinline__
void gemm_body(const float* __restrict__ X,
               const float* __restrict__ W,
               const float* __restrict__ bias,
               float* __restrict__ out,
               int bx, int by)
{
    __shared__ float As[2][128 * ASTR];
    __shared__ float Bs[2][16 * BSTR];

    const int tid  = threadIdx.x;
    const int wid  = tid >> 5;
    const int lane = tid & 31;
    const int g    = lane >> 2;
    const int t4   = lane & 3;
    const int m0   = (wid & 1) * 64;
    const int n0   = (wid >> 1) * 32;

    const int am  = tid >> 1;
    const int ak  = (tid & 1) * 8;
    const int bkr = tid >> 4;
    const int bn8 = (tid & 15) * 8;

    const float* Xp = X + (size_t)(by * 128 + am) * DMODEL;
    const float* Wp = W + bx * 128 + (size_t)bkr * DMODEL + bn8;

    uint32_t a_dst[2], b_dst[2];
    a_dst[0] = s2u(&As[0][am * ASTR + ak]);
    a_dst[1] = s2u(&As[1][am * ASTR + ak]);
    b_dst[0] = s2u(&Bs[0][bkr * BSTR + bn8]);
    b_dst[1] = s2u(&Bs[1][bkr * BSTR + bn8]);

    float acc[4][4][4];
    #pragma unroll
    for (int i = 0; i < 4; i++)
        #pragma unroll
        for (int j = 0; j < 4; j++)
            #pragma unroll
            for (int r = 0; r < 4; r++) acc[i][j][r] = 0.f;

    cp16(a_dst[0], Xp + ak);
    cp16(a_dst[0] + 16, Xp + ak + 4);
    cp16(b_dst[0], Wp);
    cp16(b_dst[0] + 16, Wp + 4);
    cp_commit();

    const int a_lrow = lane & 15;
    const int a_koff = (lane >> 4) << 2;

    for (int t = 0; t < DMODEL / 16; ++t) {
        const int cur = t & 1;
        if (t < DMODEL / 16 - 1) {
            const int nx = (t + 1) & 1;
            const int nk = (t + 1) * 16;
            cp16(a_dst[nx], Xp + nk + ak);
            cp16(a_dst[nx] + 16, Xp + nk + ak + 4);
            const float* wsrc = Wp + (size_t)nk * DMODEL;
            cp16(b_dst[nx], wsrc);
            cp16(b_dst[nx] + 16, wsrc + 4);
            cp_commit();
            cp_wait<1>();
        } else {
            cp_wait<0>();
        }
        __syncthreads();

        const float* as = As[cur];
        const float* bs = Bs[cur];
        #pragma unroll
        for (int kk = 0; kk < 16; kk += 8) {
            uint32_t af[4][4], bf[4][2];
            #pragma unroll
            for (int i = 0; i < 4; i++) {
                uint32_t ad = s2u(&as[(m0 + i * 16 + a_lrow) * ASTR + kk + a_koff]);
                ldsm4(af[i], ad);
            }
            #pragma unroll
            for (int j = 0; j < 4; j++) {
                bf[j][0] = __float_as_uint(bs[(kk + t4) * BSTR + n0 + j * 8 + g]);
                bf[j][1] = __float_as_uint(bs[(kk + t4 + 4) * BSTR + n0 + j * 8 + g]);
            }
            #pragma unroll
            for (int i = 0; i < 4; i++)
                #pragma unroll
                for (int j = 0; j < 4; j++)
                    mma_tf32(acc[i][j], af[i], bf[j]);
        }
        __syncthreads();
    }

    #pragma unroll
    for (int i = 0; i < 4; i++) {
        const int Ra = by * 128 + m0 + i * 16 + g;
        #pragma unroll
        for (int j = 0; j < 4; j++) {
            const int c = bx * 128 + n0 + j * 8 + 2 * t4;
            const float b0v = bias[c], b1v = bias[c + 1];
            float2 v0, v1;
            if (HEADOUT) {   // q/k/v are MMA inputs downstream: round to tf32
                v0 = {f2tf(acc[i][j][0] + b0v), f2tf(acc[i][j][1] + b1v)};
                v1 = {f2tf(acc[i][j][2] + b0v), f2tf(acc[i][j][3] + b1v)};
            } else {         // final output: full fp32
                v0 = {acc[i][j][0] + b0v, acc[i][j][1] + b1v};
                v1 = {acc[i][j][2] + b0v, acc[i][j][3] + b1v};
            }
            if (HEADOUT) {
                const int h = c >> 6, d = c & 63;
                {
                    const int bb = Ra >> 11, s = Ra & 2047;
                    *(float2*)&out[(((size_t)(bb * NHEADS + h) * SEQ) + s) * HDIM + d] = v0;
                }
                {
                    const int R2 = Ra + 8;
                    const int bb = R2 >> 11, s = R2 & 2047;
                    *(float2*)&out[(((size_t)(bb * NHEADS + h) * SEQ) + s) * HDIM + d] = v1;
                }
            } else {
                *(float2*)&out[(size_t)Ra * DMODEL + c] = v0;
                *(float2*)&out[(size_t)(Ra + 8) * DMODEL + c] = v1;
            }
        }
    }
}

__global__ __launch_bounds__(256, 2)
void gemm_qkv(const float* __restrict__ X,
              const float* __restrict__ Wq, const float* __restrict__ bq, float* __restrict__ q,
              const float* __restrict__ Wk, const float* __restrict__ bk, float* __restrict__ k,
              const float* __restrict__ Wv, const float* __restrict__ bv, float* __restrict__ v)
{
    const int z = blockIdx.z;
    const float* W  = (z == 0) ? Wq : (z == 1) ? Wk : Wv;
    const float* bb = (z == 0) ? bq : (z == 1) ? bk : bv;
    float*       o  = (z == 0) ? q  : (z == 1) ? k  : v;
    gemm_body<true>(X, W, bb, o, blockIdx.x, blockIdx.y);
}

__global__ __launch_bounds__(256, 2)
void gemm_out(const float* __restrict__ X,
              const float* __restrict__ W,
              const float* __restrict__ bias,
              float* __restrict__ out)
{
    gemm_body<false>(X, W, bias, out, blockIdx.x, blockIdx.y);
}

// ========== Flash attention, tf32 tensor cores, 2-stage cp.async KV ==========
// 256 threads (8 warps), q-tile 128 rows, warp owns m16. KV tiles of 64.
// Q/K/V arrive pre-rounded to tf32.
#define QST 68
#define KST 68
#define VST 72
#define KWORDS (64 * KST)
#define VWORDS (64 * VST)

__global__ __launch_bounds__(256, 2)
void attn_tf32(const float* __restrict__ Q,
               const float* __restrict__ K,
               const float* __restrict__ V,
               float* __restrict__ out)
{
    extern __shared__ float sm[];
    float* QP  = sm;                         // 128 x QST
    float* Ks0 = sm + 128 * QST;
    float* Ks1 = Ks0 + KWORDS;
    float* Vs0 = Ks1 + KWORDS;
    float* Vs1 = Vs0 + VWORDS;
    float* Ksb[2] = {Ks0, Ks1};
    float* Vsb[2] = {Vs0, Vs1};

    const int tid  = threadIdx.x;
    const int wid  = tid >> 5;
    const int lane = tid & 31;
    const int g    = lane >> 2;
    const int t4   = lane & 3;
    const int m0   = wid * 16;

    const int qt = blockIdx.x;
    const int h  = blockIdx.y;
    const int bz = blockIdx.z;

    const size_t base = ((size_t)(bz * NHEADS + h)) * SEQ * HDIM;
    const float* Qg = Q + base + (size_t)qt * 128 * HDIM;
    const float* Kb = K + base;
    const float* Vb = V + base;

    const int kvrow = tid >> 2;
    const int kvc   = (tid & 3) * 16;
    const int kvoff = kvrow * HDIM + kvc;
    uint32_t kdst[2], vdst[2];
    kdst[0] = s2u(&Ks0[kvrow * KST + kvc]);
    kdst[1] = s2u(&Ks1[kvrow * KST + kvc]);
    vdst[0] = s2u(&Vs0[kvrow * VST + kvc]);
    vdst[1] = s2u(&Vs1[kvrow * VST + kvc]);

    {
        const float* ks = Kb + kvoff;
        const float* vs = Vb + kvoff;
        #pragma unroll
        for (int c = 0; c < 16; c += 4) {
            cp16(kdst[0] + c * 4, ks + c);
            cp16(vdst[0] + c * 4, vs + c);
        }
        cp_commit();
    }

    #pragma unroll
    for (int it = 0; it < 8; ++it) {
        const int lin = tid + it * 256;
        const int row = lin >> 4, d4 = (lin & 15) * 4;
        *(float4*)&QP[row * QST + d4] = *(const float4*)(Qg + row * HDIM + d4);
    }
    __syncthreads();

    uint32_t qa[8][4];
    {
        const int ra = m0 + g;
        #pragma unroll
        for (int k8 = 0; k8 < 8; k8++) {
            const int kb = k8 * 8;
            qa[k8][0] = __float_as_uint(QP[ra * QST + kb + t4]);
            qa[k8][1] = __float_as_uint(QP[(ra + 8) * QST + kb + t4]);
            qa[k8][2] = __float_as_uint(QP[ra * QST + kb + t4 + 4]);
            qa[k8][3] = __float_as_uint(QP[(ra + 8) * QST + kb + t4 + 4]);
        }
    }

    float om[2] = {-1e30f, -1e30f}, ol[2] = {0.f, 0.f};
    float oacc[8][4];
    #pragma unroll
    for (int j = 0; j < 8; j++)
        #pragma unroll
        for (int r = 0; r < 4; r++) oacc[j][r] = 0.f;

    const int k_rsub = ((lane >> 4) & 1) * 8 + (lane & 7);
    const int k_coff = ((lane >> 3) & 1) * 4;
    const int p_row  = m0 + (lane & 15);
    const int p_coff = (lane >> 4) << 2;

    for (int kt = 0; kt < SEQ / 64; kt++) {
        const int cur = kt & 1;
        if (kt + 1 < SEQ / 64) {
            const int nx = (kt + 1) & 1;
            const float* ks = Kb + (size_t)(kt + 1) * 64 * HDIM + kvoff;
            const float* vs = Vb + (size_t)(kt + 1) * 64 * HDIM + kvoff;
            #pragma unroll
            for (int c = 0; c < 16; c += 4) {
                cp16(kdst[nx] + c * 4, ks + c);
                cp16(vdst[nx] + c * 4, vs + c);
            }
            cp_commit();
            cp_wait<1>();
        } else {
            cp_wait<0>();
        }
        __syncthreads();

        const float* ks = Ksb[cur];
        const float* vs = Vsb[cur];

        float s[8][4];
        #pragma unroll
        for (int j = 0; j < 8; j++)
            #pragma unroll
            for (int r = 0; r < 4; r++) s[j][r] = 0.f;

        #pragma unroll
        for (int k8 = 0; k8 < 8; k8++) {
            const int kb = k8 * 8;
            uint32_t bf[8][2];
            #pragma unroll
            for (int jj = 0; jj < 8; jj += 2) {
                uint32_t r[4];
                ldsm4(r, s2u(&ks[(jj * 8 + k_rsub) * KST + kb + k_coff]));
                bf[jj][0] = r[0]; bf[jj][1] = r[1];
                bf[jj + 1][0] = r[2]; bf[jj + 1][1] = r[3];
            }
            #pragma unroll
            for (int j = 0; j < 8; j++)
                mma_tf32(s[j], qa[k8], bf[j]);
        }

        #pragma unroll
        for (int hf = 0; hf < 2; hf++) {
            float mx = -1e30f;
            #pragma unroll
            for (int j = 0; j < 8; j++) {
                s[j][2 * hf]     *= 0.125f;
                s[j][2 * hf + 1] *= 0.125f;
                mx = fmaxf(mx, fmaxf(s[j][2 * hf], s[j][2 * hf + 1]));
            }
            mx = fmaxf(mx, __shfl_xor_sync(0xffffffffu, mx, 1));
            mx = fmaxf(mx, __shfl_xor_sync(0xffffffffu, mx, 2));
            const float mnew = fmaxf(om[hf], mx);
            const float alpha = __expf(om[hf] - mnew);
            om[hf] = mnew;
            float sum = 0.f;
            #pragma unroll
            for (int j = 0; j < 8; j++) {
                float e0 = __expf(s[j][2 * hf] - mnew);
                float e1 = __expf(s[j][2 * hf + 1] - mnew);
                s[j][2 * hf] = e0; s[j][2 * hf + 1] = e1;
                sum += e0 + e1;
            }
            sum += __shfl_xor_sync(0xffffffffu, sum, 1);
            sum += __shfl_xor_sync(0xffffffffu, sum, 2);
            ol[hf] = ol[hf] * alpha + sum;
            #pragma unroll
            for (int j = 0; j < 8; j++) {
                oacc[j][2 * hf]     *= alpha;
                oacc[j][2 * hf + 1] *= alpha;
            }
        }

        // store P rounded to tf32 (it is an MMA A-operand)
        {
            const int ra = m0 + g;
            #pragma unroll
            for (int j = 0; j < 8; j++) {
                const int col = j * 8 + 2 * t4;
                *(float2*)&QP[ra * QST + col]       = make_float2(f2tf(s[j][0]), f2tf(s[j][1]));
                *(float2*)&QP[(ra + 8) * QST + col] = make_float2(f2tf(s[j][2]), f2tf(s[j][3]));
            }
        }
        __syncwarp();

        #pragma unroll
        for (int k8 = 0; k8 < 8; k8++) {
            const int kb = k8 * 8;
            uint32_t pa[4], vb[8][2];
            ldsm4(pa, s2u(&QP[p_row * QST + kb + p_coff]));
            #pragma unroll
            for (int j = 0; j < 8; j++) {
                vb[j][0] = __float_as_uint(vs[(kb + t4) * VST + j * 8 + g]);
                vb[j][1] = __float_as_uint(vs[(kb + t4 + 4) * VST + j * 8 + g]);
            }
            #pragma unroll
            for (int j = 0; j < 8; j++)
                mma_tf32(oacc[j], pa, vb[j]);
        }
        __syncthreads();
    }

    // epilogue: att is an MMA input downstream -> round to tf32
    #pragma unroll
    for (int hf = 0; hf < 2; hf++) {
        const float inv = 1.f / ol[hf];
        const int row = qt * 128 + m0 + g + hf * 8;
        float* og = out + ((size_t)bz * SEQ + row) * DMODEL + h * HDIM;
        #pragma unroll
        for (int j = 0; j < 8; j++) {
            const int c = j * 8 + 2 * t4;
            float2 v = {f2tf(oacc[j][2 * hf] * inv), f2tf(oacc[j][2 * hf + 1] * inv)};
            *(float2*)&og[c] = v;
        }
    }
}

// ============================== launch ==============================
extern "C" void kernel_launch(void* const* d_in, const int* in_sizes, int n_in,
                              void* d_out, int out_size)
{
    const float* X  = (const float*)d_in[0];
    const float* Wq = (const float*)d_in[1];
    const float* bq = (const float*)d_in[2];
    const float* Wk = (const float*)d_in[3];
    const float* bk = (const float*)d_in[4];
    const float* Wv = (const float*)d_in[5];
    const float* bv = (const float*)d_in[6];
    const float* Wo = (const float*)d_in[7];
    const float* bo = (const float*)d_in[8];

    float *qp, *kp, *vp, *ap, *xp, *wqp, *wkp, *wvp, *wop;
    cudaGetSymbolAddress((void**)&qp, g_q);
    cudaGetSymbolAddress((void**)&kp, g_k);
    cudaGetSymbolAddress((void**)&vp, g_v);
    cudaGetSymbolAddress((void**)&ap, g_att);
    cudaGetSymbolAddress((void**)&xp, g_x);
    cudaGetSymbolAddress((void**)&wqp, g_wq);
    cudaGetSymbolAddress((void**)&wkp, g_wk);
    cudaGetSymbolAddress((void**)&wvp, g_wv);
    cudaGetSymbolAddress((void**)&wop, g_wo);

    // pre-pass: round X + weights to tf32
    {
        const int n4max = MROWS * DMODEL / 4;   // 1M float4
        dim3 rg((n4max + 255) / 256, 1, 5);
        round_inputs<<<rg, 256>>>(X, Wq, Wk, Wv, Wo, xp, wqp, wkp, wvp, wop);
    }

    dim3 qkvgrid(DMODEL / 128, MROWS / 128, 3);
    gemm_qkv<<<qkvgrid, 256>>>(xp, wqp, bq, qp, wkp, bk, kp, wvp, bv, vp);

    const size_t smem = (size_t)(128 * QST + 2 * KWORDS + 2 * VWORDS) * sizeof(float); // 106496 B
    cudaFuncSetAttribute(attn_tf32, cudaFuncAttributeMaxDynamicSharedMemorySize, (int)smem);
    attn_tf32<<<dim3(SEQ / 128, NHEADS, BATCH), 256, smem>>>(qp, kp, vp, ap);

    gemm_out<<<dim3(DMODEL / 128, MROWS / 128), 256>>>(ap, wop, bo, (float*)d_out);
}

// round 8
// speedup vs baseline: 1.0655x; 1.0655x over previous
#include <cuda_runtime.h>
#include <cstdint>

#define BATCH   2
#define SEQ     2048
#define DMODEL  1024
#define NHEADS  16
#define HDIM    64
#define MROWS   (BATCH*SEQ)   // 4096

// -------- scratch (device globals; no allocation allowed) --------
__device__ float g_q[BATCH*NHEADS*SEQ*HDIM];   // [b][h][s][d]  (tf32-rounded)
__device__ float g_k[BATCH*NHEADS*SEQ*HDIM];
__device__ float g_v[BATCH*NHEADS*SEQ*HDIM];
__device__ float g_att[MROWS*DMODEL];          // merged [b][s][h*64+d] (tf32-rounded)

// ---------------- PTX helpers ----------------
__device__ __forceinline__ uint32_t s2u(const void* p) {
    return (uint32_t)__cvta_generic_to_shared(p);
}
__device__ __forceinline__ void cp16(uint32_t dst, const void* src) {
    asm volatile("cp.async.cg.shared.global [%0], [%1], 16;" :: "r"(dst), "l"(src));
}
__device__ __forceinline__ void cp_commit() {
    asm volatile("cp.async.commit_group;");
}
template<int N> __device__ __forceinline__ void cp_wait() {
    asm volatile("cp.async.wait_group %0;" :: "n"(N));
}
__device__ __forceinline__ void ldsm4(uint32_t* r, uint32_t addr) {
    asm volatile("ldmatrix.sync.aligned.m8n8.x4.shared.b16 {%0,%1,%2,%3}, [%4];"
                 : "=r"(r[0]), "=r"(r[1]), "=r"(r[2]), "=r"(r[3]) : "r"(addr));
}
// round-to-nearest tf32; result is an fp32 bit pattern
__device__ __forceinline__ float f2tf(float x) {
    uint32_t r;
    asm("cvt.rna.tf32.f32 %0, %1;" : "=r"(r) : "f"(x));
    return __uint_as_float(r);
}
__device__ __forceinline__ uint32_t u2tf(uint32_t x) {
    uint32_t r;
    asm("cvt.rna.tf32.f32 %0, %1;" : "=r"(r) : "f"(__uint_as_float(x)));
    return r;
}

// D += A * B  (m16n8k8, A row-major, B col-major, fp32 accum)
__device__ __forceinline__ void mma_tf32(float* d, const uint32_t* a, const uint32_t* b) {
    asm volatile(
        "mma.sync.aligned.m16n8k8.row.col.f32.tf32.tf32.f32 "
        "{%0,%1,%2,%3}, {%4,%5,%6,%7}, {%8,%9}, {%0,%1,%2,%3};\n"
        : "+f"(d[0]), "+f"(d[1]), "+f"(d[2]), "+f"(d[3])
        : "r"(a[0]), "r"(a[1]), "r"(a[2]), "r"(a[3]),
          "r"(b[0]), "r"(b[1]));
}

// ================= GEMM (tf32 tensor core), 4-stage cp.async ==========
// M=4096, N=K=1024. Block 128x128, BK=16, 256 threads = 8 warps (2x4),
// warp tile 64x32. tf32 rounding applied in registers (CVTA/CVTB).
#define ASTR 20          // As[m][k] row stride (words)
#define BSTR 136         // Bs[k][n] row stride (words)
#define AWORDS (128 * ASTR)              // 2560
#define STG_WORDS (AWORDS + 16 * BSTR)   // 4736
#define STG_BYTES (STG_WORDS * 4)        // 18944
#define NSTAGE 4
#define GSMEM_BYTES (NSTAGE * STG_BYTES) // 75776

template<bool CVTA, bool CVTB, bool HEADOUT>
__device__ __forceinline__
void gemm_body(const float* __restrict__ X,
               const float* __restrict__ W,
               const float* __restrict__ bias,
               float* __restrict__ out,
               int bx, int by)
{
    extern __shared__ float gsm[];

    const int tid  = threadIdx.x;
    const int wid  = tid >> 5;
    const int lane = tid & 31;
    const int g    = lane >> 2;
    const int t4   = lane & 3;
    const int m0   = (wid & 1) * 64;
    const int n0   = (wid >> 1) * 32;

    const int am  = tid >> 1;          // A row 0..127
    const int ak  = (tid & 1) * 8;     // A k-chunk base (8 floats)
    const int bkr = tid >> 4;          // B k-row 0..15
    const int bn8 = (tid & 15) * 8;    // B n-chunk base (8 floats)

    const float* Xp = X + (size_t)(by * 128 + am) * DMODEL + ak;
    const float* Wp = W + bx * 128 + (size_t)bkr * DMODEL + bn8;

    const uint32_t a_base = s2u(gsm + am * ASTR + ak);
    const uint32_t b_base = s2u(gsm + AWORDS + bkr * BSTR + bn8);

    float acc[4][4][4];
    #pragma unroll
    for (int i = 0; i < 4; i++)
        #pragma unroll
        for (int j = 0; j < 4; j++)
            #pragma unroll
            for (int r = 0; r < 4; r++) acc[i][j][r] = 0.f;

    const int T = DMODEL / 16;   // 64

    // prologue: issue stages 0..2
    #pragma unroll
    for (int p = 0; p < NSTAGE - 1; ++p) {
        const uint32_t ad = a_base + p * STG_BYTES;
        const uint32_t bd = b_base + p * STG_BYTES;
        const float* xs = Xp + p * 16;
        const float* ws = Wp + (size_t)p * 16 * DMODEL;
        cp16(ad, xs);       cp16(ad + 16, xs + 4);
        cp16(bd, ws);       cp16(bd + 16, ws + 4);
        cp_commit();
    }

    const int a_lrow = lane & 15;
    const int a_koff = (lane >> 4) << 2;

    for (int t = 0; t < T; ++t) {
        cp_wait<NSTAGE - 2>();
        __syncthreads();

        // issue tile t+3 into stage (t+3)%4 (that buffer was consumed in iter t-1)
        if (t + NSTAGE - 1 < T) {
            const int sn = (t + NSTAGE - 1) & (NSTAGE - 1);
            const uint32_t ad = a_base + sn * STG_BYTES;
            const uint32_t bd = b_base + sn * STG_BYTES;
            const float* xs = Xp + (t + NSTAGE - 1) * 16;
            const float* ws = Wp + (size_t)(t + NSTAGE - 1) * 16 * DMODEL;
            cp16(ad, xs);       cp16(ad + 16, xs + 4);
            cp16(bd, ws);       cp16(bd + 16, ws + 4);
        }
        cp_commit();   // always commit (possibly empty) to keep group count sound

        const float* as = gsm + (t & (NSTAGE - 1)) * STG_WORDS;
        const float* bs = as + AWORDS;

        #pragma unroll
        for (int kk = 0; kk < 16; kk += 8) {
            uint32_t af[4][4], bf[4][2];
            #pragma unroll
            for (int i = 0; i < 4; i++) {
                uint32_t ad = s2u(&as[(m0 + i * 16 + a_lrow) * ASTR + kk + a_koff]);
                ldsm4(af[i], ad);
            }
            #pragma unroll
            for (int j = 0; j < 4; j++) {
                bf[j][0] = __float_as_uint(bs[(kk + t4) * BSTR + n0 + j * 8 + g]);
                bf[j][1] = __float_as_uint(bs[(kk + t4 + 4) * BSTR + n0 + j * 8 + g]);
            }
            if (CVTA) {
                #pragma unroll
                for (int i = 0; i < 4; i++)
                    #pragma unroll
                    for (int r = 0; r < 4; r++) af[i][r] = u2tf(af[i][r]);
            }
            if (CVTB) {
                #pragma unroll
                for (int j = 0; j < 4; j++) {
                    bf[j][0] = u2tf(bf[j][0]);
                    bf[j][1] = u2tf(bf[j][1]);
                }
            }
            #pragma unroll
            for (int i = 0; i < 4; i++)
                #pragma unroll
                for (int j = 0; j < 4; j++)
                    mma_tf32(acc[i][j], af[i], bf[j]);
        }
    }

    // epilogue
    #pragma unroll
    for (int i = 0; i < 4; i++) {
        const int Ra = by * 128 + m0 + i * 16 + g;
        #pragma unroll
        for (int j = 0; j < 4; j++) {
            const int c = bx * 128 + n0 + j * 8 + 2 * t4;
            const float b0v = bias[c], b1v = bias[c + 1];
            float2 v0, v1;
            if (HEADOUT) {   // q/k/v feed MMAs downstream: round to tf32
                v0 = {f2tf(acc[i][j][0] + b0v), f2tf(acc[i][j][1] + b1v)};
                v1 = {f2tf(acc[i][j][2] + b0v), f2tf(acc[i][j][3] + b1v)};
            } else {
                v0 = {acc[i][j][0] + b0v, acc[i][j][1] + b1v};
                v1 = {acc[i][j][2] + b0v, acc[i][j][3] + b1v};
            }
            if (HEADOUT) {
                const int h = c >> 6, d = c & 63;
                {
                    const int bb = Ra >> 11, s = Ra & 2047;
                    *(float2*)&out[(((size_t)(bb * NHEADS + h) * SEQ) + s) * HDIM + d] = v0;
                }
                {
                    const int R2 = Ra + 8;
                    const int bb = R2 >> 11, s = R2 & 2047;
                    *(float2*)&out[(((size_t)(bb * NHEADS + h) * SEQ) + s) * HDIM + d] = v1;
                }
            } else {
                *(float2*)&out[(size_t)Ra * DMODEL + c] = v0;
                *(float2*)&out[(size_t)(Ra + 8) * DMODEL + c] = v1;
            }
        }
    }
}

__global__ __launch_bounds__(256, 2)
void gemm_qkv(const float* __restrict__ X,
              const float* __restrict__ Wq, const float* __restrict__ bq, float* __restrict__ q,
              const float* __restrict__ Wk, const float* __restrict__ bk, float* __restrict__ k,
              const float* __restrict__ Wv, const float* __restrict__ bv, float* __restrict__ v)
{
    const int z = blockIdx.z;
    const float* W  = (z == 0) ? Wq : (z == 1) ? Wk : Wv;
    const float* bb = (z == 0) ? bq : (z == 1) ? bk : bv;
    float*       o  = (z == 0) ? q  : (z == 1) ? k  : v;
    gemm_body<true, true, true>(X, W, bb, o, blockIdx.x, blockIdx.y);
}

__global__ __launch_bounds__(256, 2)
void gemm_out(const float* __restrict__ X,    // g_att, already tf32-rounded
              const float* __restrict__ W,
              const float* __restrict__ bias,
              float* __restrict__ out)
{
    gemm_body<false, true, false>(X, W, bias, out, blockIdx.x, blockIdx.y);
}

// ========== Flash attention, tf32 tensor cores, 2-stage cp.async KV ==========
// 256 threads (8 warps), q-tile 128 rows, warp owns m16. KV tiles of 64.
// Q/K/V arrive pre-rounded to tf32.
#define QST 68
#define KST 68
#define VST 72
#define KWORDS (64 * KST)
#define VWORDS (64 * VST)

__global__ __launch_bounds__(256, 2)
void attn_tf32(const float* __restrict__ Q,
               const float* __restrict__ K,
               const float* __restrict__ V,
               float* __restrict__ out)
{
    extern __shared__ float sm[];
    float* QP  = sm;                         // 128 x QST
    float* Ks0 = sm + 128 * QST;             // 2 stages of K, then 2 of V
    float* Vs0 = Ks0 + 2 * KWORDS;

    const int tid  = threadIdx.x;
    const int wid  = tid >> 5;
    const int lane = tid & 31;
    const int g    = lane >> 2;
    const int t4   = lane & 3;
    const int m0   = wid * 16;

    const int qt = blockIdx.x;
    const int h  = blockIdx.y;
    const int bz = blockIdx.z;

    const size_t base = ((size_t)(bz * NHEADS + h)) * SEQ * HDIM;
    const float* Qg = Q + base + (size_t)qt * 128 * HDIM;
    const float* Kb = K + base;
    const float* Vb = V + base;

    // KV copy: row = tid>>2 (0..63), chunk base = (tid&3)*16 floats
    const int kvrow = tid >> 2;
    const int kvc   = (tid & 3) * 16;
    const int kvoff = kvrow * HDIM + kvc;
    const uint32_t kdst0 = s2u(&Ks0[kvrow * KST + kvc]);
    const uint32_t vdst0 = s2u(&Vs0[kvrow * VST + kvc]);

    // prologue: prefetch KV tile 0 into stage 0  (byte offset = c floats * 4)
    {
        const float* ks = Kb + kvoff;
        const float* vs = Vb + kvoff;
        #pragma unroll
        for (int c = 0; c < 16; c += 4) {
            cp16(kdst0 + c * 4, ks + c);
            cp16(vdst0 + c * 4, vs + c);
        }
        cp_commit();
    }

    #pragma unroll
    for (int it = 0; it < 8; ++it) {
        const int lin = tid + it * 256;
        const int row = lin >> 4, d4 = (lin & 15) * 4;
        *(float4*)&QP[row * QST + d4] = *(const float4*)(Qg + row * HDIM + d4);
    }
    __syncthreads();

    uint32_t qa[8][4];
    {
        const int ra = m0 + g;
        #pragma unroll
        for (int k8 = 0; k8 < 8; k8++) {
            const int kb = k8 * 8;
            qa[k8][0] = __float_as_uint(QP[ra * QST + kb + t4]);
            qa[k8][1] = __float_as_uint(QP[(ra + 8) * QST + kb + t4]);
            qa[k8][2] = __float_as_uint(QP[ra * QST + kb + t4 + 4]);
            qa[k8][3] = __float_as_uint(QP[(ra + 8) * QST + kb + t4 + 4]);
        }
    }

    float om[2] = {-1e30f, -1e30f}, ol[2] = {0.f, 0.f};
    float oacc[8][4];
    #pragma unroll
    for (int j = 0; j < 8; j++)
        #pragma unroll
        for (int r = 0; r < 4; r++) oacc[j][r] = 0.f;

    const int k_rsub = ((lane >> 4) & 1) * 8 + (lane & 7);
    const int k_coff = ((lane >> 3) & 1) * 4;
    const int p_row  = m0 + (lane & 15);
    const int p_coff = (lane >> 4) << 2;

    for (int kt = 0; kt < SEQ / 64; kt++) {
        const int cur = kt & 1;
        if (kt + 1 < SEQ / 64) {
            const int nx = cur ^ 1;
            const float* ks = Kb + (size_t)(kt + 1) * 64 * HDIM + kvoff;
            const float* vs = Vb + (size_t)(kt + 1) * 64 * HDIM + kvoff;
            const uint32_t kd = kdst0 + nx * (KWORDS * 4);
            const uint32_t vd = vdst0 + nx * (VWORDS * 4);
            #pragma unroll
            for (int c = 0; c < 16; c += 4) {
                cp16(kd + c * 4, ks + c);
                cp16(vd + c * 4, vs + c);
            }
            cp_commit();
            cp_wait<1>();
        } else {
            cp_wait<0>();
        }
        __syncthreads();

        const float* ks = Ks0 + cur * KWORDS;
        const float* vs = Vs0 + cur * VWORDS;

        float s[8][4];
        #pragma unroll
        for (int j = 0; j < 8; j++)
            #pragma unroll
            for (int r = 0; r < 4; r++) s[j][r] = 0.f;

        #pragma unroll
        for (int k8 = 0; k8 < 8; k8++) {
            const int kb = k8 * 8;
            uint32_t bf[8][2];
            #pragma unroll
            for (int jj = 0; jj < 8; jj += 2) {
                uint32_t r[4];
                ldsm4(r, s2u(&ks[(jj * 8 + k_rsub) * KST + kb + k_coff]));
                bf[jj][0] = r[0]; bf[jj][1] = r[1];
                bf[jj + 1][0] = r[2]; bf[jj + 1][1] = r[3];
            }
            #pragma unroll
            for (int j = 0; j < 8; j++)
                mma_tf32(s[j], qa[k8], bf[j]);
        }

        #pragma unroll
        for (int hf = 0; hf < 2; hf++) {
            float mx = -1e30f;
            #pragma unroll
            for (int j = 0; j < 8; j++) {
                s[j][2 * hf]     *= 0.125f;
                s[j][2 * hf + 1] *= 0.125f;
                mx = fmaxf(mx, fmaxf(s[j][2 * hf], s[j][2 * hf + 1]));
            }
            mx = fmaxf(mx, __shfl_xor_sync(0xffffffffu, mx, 1));
            mx = fmaxf(mx, __shfl_xor_sync(0xffffffffu, mx, 2));
            const float mnew = fmaxf(om[hf], mx);
            const float alpha = __expf(om[hf] - mnew);
            om[hf] = mnew;
            float sum = 0.f;
            #pragma unroll
            for (int j = 0; j < 8; j++) {
                float e0 = __expf(s[j][2 * hf] - mnew);
                float e1 = __expf(s[j][2 * hf + 1] - mnew);
                s[j][2 * hf] = e0; s[j][2 * hf + 1] = e1;
                sum += e0 + e1;
            }
            sum += __shfl_xor_sync(0xffffffffu, sum, 1);
            sum += __shfl_xor_sync(0xffffffffu, sum, 2);
            ol[hf] = ol[hf] * alpha + sum;
            #pragma unroll
            for (int j = 0; j < 8; j++) {
                oacc[j][2 * hf]     *= alpha;
                oacc[j][2 * hf + 1] *= alpha;
            }
        }

        // store P rounded to tf32 (it is an MMA A-operand)
        {
            const int ra = m0 + g;
            #pragma unroll
            for (int j = 0; j < 8; j++) {
                const int col = j * 8 + 2 * t4;
                *(float2*)&QP[ra * QST + col]       = make_float2(f2tf(s[j][0]), f2tf(s[j][1]));
                *(float2*)&QP[(ra + 8) * QST + col] = make_float2(f2tf(s[j][2]), f2tf(s[j][3]));
            }
        }
        __syncwarp();

        #pragma unroll
        for (int k8 = 0; k8 < 8; k8++) {
            const int kb = k8 * 8;
            uint32_t pa[4], vb[8][2];
            ldsm4(pa, s2u(&QP[p_row * QST + kb + p_coff]));
            #pragma unroll
            for (int j = 0; j < 8; j++) {
                vb[j][0] = __float_as_uint(vs[(kb + t4) * VST + j * 8 + g]);
                vb[j][1] = __float_as_uint(vs[(kb + t4 + 4) * VST + j * 8 + g]);
            }
            #pragma unroll
            for (int j = 0; j < 8; j++)
                mma_tf32(oacc[j], pa, vb[j]);
        }
        __syncthreads();   // stage cur fully consumed before refill next iter
    }

    // epilogue: att feeds gemm_out MMAs -> round to tf32
    #pragma unroll
    for (int hf = 0; hf < 2; hf++) {
        const float inv = 1.f / ol[hf];
        const int row = qt * 128 + m0 + g + hf * 8;
        float* og = out + ((size_t)bz * SEQ + row) * DMODEL + h * HDIM;
        #pragma unroll
        for (int j = 0; j < 8; j++) {
            const int c = j * 8 + 2 * t4;
            float2 v = {f2tf(oacc[j][2 * hf] * inv), f2tf(oacc[j][2 * hf + 1] * inv)};
            *(float2*)&og[c] = v;
        }
    }
}

// ============================== launch ==============================
extern "C" void kernel_launch(void* const* d_in, const int* in_sizes, int n_in,
                              void* d_out, int out_size)
{
    const float* X  = (const float*)d_in[0];
    const float* Wq = (const float*)d_in[1];
    const float* bq = (const float*)d_in[2];
    const float* Wk = (const float*)d_in[3];
    const float* bk = (const float*)d_in[4];
    const float* Wv = (const float*)d_in[5];
    const float* bv = (const float*)d_in[6];
    const float* Wo = (const float*)d_in[7];
    const float* bo = (const float*)d_in[8];

    float *qp, *kp, *vp, *ap;
    cudaGetSymbolAddress((void**)&qp, g_q);
    cudaGetSymbolAddress((void**)&kp, g_k);
    cudaGetSymbolAddress((void**)&vp, g_v);
    cudaGetSymbolAddress((void**)&ap, g_att);

    cudaFuncSetAttribute(gemm_qkv, cudaFuncAttributeMaxDynamicSharedMemorySize, GSMEM_BYTES);
    cudaFuncSetAttribute(gemm_out, cudaFuncAttributeMaxDynamicSharedMemorySize, GSMEM_BYTES);

    dim3 qkvgrid(DMODEL / 128, MROWS / 128, 3);
    gemm_qkv<<<qkvgrid, 256, GSMEM_BYTES>>>(X, Wq, bq, qp, Wk, bk, kp, Wv, bv, vp);

    const size_t smem = (size_t)(128 * QST + 2 * KWORDS + 2 * VWORDS) * sizeof(float); // 106496 B
    cudaFuncSetAttribute(attn_tf32, cudaFuncAttributeMaxDynamicSharedMemorySize, (int)smem);
    attn_tf32<<<dim3(SEQ / 128, NHEADS, BATCH), 256, smem>>>(qp, kp, vp, ap);

    gemm_out<<<dim3(DMODEL / 128, MROWS / 128), 256, GSMEM_BYTES>>>(ap, Wo, bo, (float*)d_out);
}